// round 1
// baseline (speedup 1.0000x reference)
#include <cuda_runtime.h>
#include <math.h>

// Problem constants (fixed by the dataset): N_kc=1024, F=128.
#define NKC 1024
#define F   128
#define BM  48      // exercise rows per CTA
#define TJ  32      // kc tile (j dimension) per iteration
#define NT  128     // threads per CTA  (8 ty-groups x 16 tx)

// Scratch (device globals: no allocation allowed)
__device__ float g_kcWh[NKC*F];
__device__ float g_q[NKC];
__device__ float g_v1[F];
__device__ float g_qmax;

// ---- packed f32x2 helpers (FFMA2 — only reachable via PTX) ----
__device__ __forceinline__ unsigned long long pk2(float a, float b){
  unsigned long long r; asm("mov.b64 %0, {%1,%2};" : "=l"(r) : "f"(a), "f"(b)); return r;
}
__device__ __forceinline__ void fma2(unsigned long long &d, unsigned long long a, unsigned long long b){
  asm("fma.rn.f32x2 %0, %1, %2, %0;" : "+l"(d) : "l"(a), "l"(b));
}
__device__ __forceinline__ float2 upk2(unsigned long long v){
  float2 r; asm("mov.b64 {%0,%1}, %2;" : "=f"(r.x), "=f"(r.y) : "l"(v)); return r;
}
__device__ __forceinline__ float eluf(float x){ return x > 0.f ? x : expm1f(x); }

// ---------------------------------------------------------------------------
// prep_kc: kc_Wh[j,:] = kc_h[j,:] @ W1 ; q[j] = kc_Wh[j,:] . a2
// grid = NKC blocks, 128 threads
// ---------------------------------------------------------------------------
__global__ void prep_kc(const float* __restrict__ kch, const float* __restrict__ W1,
                        const float* __restrict__ a){
  __shared__ float sh[F];
  __shared__ float red[4];
  int j = blockIdx.x, f = threadIdx.x;
  sh[f] = kch[j*F + f];
  __syncthreads();
  float acc = 0.f;
  #pragma unroll 16
  for (int k = 0; k < F; k++) acc = fmaf(sh[k], W1[k*F + f], acc);
  g_kcWh[j*F + f] = acc;
  float t = acc * a[F + f];                    // a2 = a[128:256]
  #pragma unroll
  for (int o = 16; o > 0; o >>= 1) t += __shfl_xor_sync(0xffffffffu, t, o);
  if ((f & 31) == 0) red[f >> 5] = t;
  __syncthreads();
  if (f == 0) g_q[j] = red[0] + red[1] + red[2] + red[3];
}

// ---------------------------------------------------------------------------
// prep_v: v1 = W1 @ a1 (so p_i = ex_h[i] . v1), plus Qmax = max_j q[j]
// grid = 1 block, 128 threads
// ---------------------------------------------------------------------------
__global__ void prep_v(const float* __restrict__ W1, const float* __restrict__ a, int nkc){
  __shared__ float red[4];
  int k = threadIdx.x;
  float v = 0.f;
  #pragma unroll 16
  for (int f = 0; f < F; f++) v = fmaf(W1[k*F + f], a[f], v);   // a1 = a[0:128]
  g_v1[k] = v;
  float mq = -3.0e38f;
  for (int i = k; i < nkc; i += NT) mq = fmaxf(mq, g_q[i]);
  #pragma unroll
  for (int o = 16; o > 0; o >>= 1) mq = fmaxf(mq, __shfl_xor_sync(0xffffffffu, mq, o));
  if ((k & 31) == 0) red[k >> 5] = mq;
  __syncthreads();
  if (k == 0) g_qmax = fmaxf(fmaxf(red[0], red[1]), fmaxf(red[2], red[3]));
}

// ---------------------------------------------------------------------------
// Main fused kernel: per CTA, BM=48 exercise rows.
//   - p_r = ex_h[r].v1 ; m_r = lrelu(p_r + Qmax)  (global-bound stabilizer)
//   - loop over kc tiles of TJ=32:
//       w[r][j] = adj ? exp(lrelu(p_r+q_j) - m_r) : 0   (single pass, l += w)
//       acc[r][:] += w[r][j] * kc_Wh[j][:]              (FFMA2 register tiles 6x8)
//   - epilogue: Eh[r][:] = ex_h[r] @ E ; out = elu(acc/l * Eh)
// Thread map: ty=tid/16 -> rows ty*6..+5 ; tx=tid%16 -> cols tx*4..+3 and 64+tx*4..+3
// ---------------------------------------------------------------------------
__global__ void __launch_bounds__(NT, 3) gat_main(
    const float* __restrict__ exh, const int* __restrict__ adj,
    const float* __restrict__ E,   float* __restrict__ out, int nex)
{
  extern __shared__ float sm[];
  float* sEx  = sm;                 // [48][132] (pad 4 floats, keeps 16B align)
  float* sKC  = sEx + BM*132;       // [32][132]
  float* sW   = sKC + TJ*132;       // [48][33]
  float* sQ   = sW  + BM*33;        // [1024]
  float* sV   = sQ  + NKC;          // [128]
  float* sP   = sV  + F;            // [48]
  float* sM   = sP  + BM;           // [48]
  float* sInv = sM  + BM;           // [48]
  float* sLp  = sInv + BM;          // [128]

  const int tid = threadIdx.x;
  const int ty = tid >> 4, tx = tid & 15;
  const int row_start = blockIdx.x * BM;

  // ---- prologue: exercise tile, q, v1 into smem ----
  {
    float4* d4 = (float4*)sEx;
    const float4* s4 = (const float4*)exh;
    #pragma unroll
    for (int it = 0; it < 12; ++it){             // 48 rows * 32 float4 = 1536
      int i = tid + NT*it;
      int r = i >> 5, c = i & 31;
      int rg = row_start + r; if (rg > nex-1) rg = nex-1;
      d4[r*33 + c] = s4[(size_t)rg*32 + c];
    }
    ((float4*)sQ)[tid]       = ((const float4*)g_q)[tid];
    ((float4*)sQ)[tid + 128] = ((const float4*)g_q)[tid + 128];
    if (tid < 32) ((float4*)sV)[tid] = ((const float4*)g_v1)[tid];
  }
  __syncthreads();
  if (tid < BM){
    float p = 0.f;
    #pragma unroll 16
    for (int k = 0; k < F; k++) p = fmaf(sEx[tid*132 + k], sV[k], p);
    sP[tid] = p;
    float x = p + g_qmax;
    sM[tid] = x > 0.f ? x : 0.2f * x;            // lrelu, slope 0.2
  }
  __syncthreads();

  // w producers: 2 threads per row (96 threads), 16 j each
  float pr = 0.f, mr = 0.f;
  const int* abase = adj;
  const int prow = tid >> 1, phalf = tid & 1;
  if (tid < 96){
    pr = sP[prow]; mr = sM[prow];
    int rg = row_start + prow; if (rg > nex-1) rg = nex-1;
    abase = adj + (size_t)rg*NKC + phalf*16;
  }

  unsigned long long acc[6][4];
  #pragma unroll
  for (int r = 0; r < 6; r++)
    #pragma unroll
    for (int c = 0; c < 4; c++) acc[r][c] = 0ull;
  float lp = 0.f;

  // prefetch tile 0 (adj from DRAM, kc_Wh tile from L2)
  int4   apf[4];
  float4 kpf[8];
  const float4* kc4 = (const float4*)g_kcWh;
  if (tid < 96){
    const int4* ap = (const int4*)abase;
    #pragma unroll
    for (int u = 0; u < 4; u++) apf[u] = ap[u];
  }
  #pragma unroll
  for (int u = 0; u < 8; u++){                   // 32 rows * 32 float4 = 1024
    int i = tid + NT*u; int jr = i >> 5, c = i & 31;
    kpf[u] = kc4[jr*32 + c];
  }

  for (int t = 0; t < NKC/TJ; t++){
    __syncthreads();                             // previous tile fully consumed
    // commit prefetched kc tile
    #pragma unroll
    for (int u = 0; u < 8; u++){
      int i = tid + NT*u; int jr = i >> 5, c = i & 31;
      ((float4*)sKC)[jr*33 + c] = kpf[u];
    }
    // compute attention weights for this tile
    if (tid < 96){
      const float* qb = sQ + t*TJ + phalf*16;
      float* wb = sW + prow*33 + phalf*16;
      #pragma unroll
      for (int u = 0; u < 4; u++){
        int4 a4 = apf[u];
        #pragma unroll
        for (int v = 0; v < 4; v++){
          int av = (v==0) ? a4.x : (v==1) ? a4.y : (v==2) ? a4.z : a4.w;
          float x = pr + qb[u*4 + v];
          float e = x > 0.f ? x : 0.2f * x;
          float w = (av > 0) ? __expf(e - mr) : 0.f;
          lp += w;
          wb[u*4 + v] = w;
        }
      }
    }
    __syncthreads();
    // prefetch next tile while GEMM runs
    if (t < NKC/TJ - 1){
      if (tid < 96){
        const int4* ap = (const int4*)(abase + (t+1)*TJ);
        #pragma unroll
        for (int u = 0; u < 4; u++) apf[u] = ap[u];
      }
      #pragma unroll
      for (int u = 0; u < 8; u++){
        int i = tid + NT*u; int jr = i >> 5, c = i & 31;
        kpf[u] = kc4[(t+1)*(TJ*32) + jr*32 + c];
      }
    }
    // GEMM: acc += w * kc_Wh  (packed f32x2)
    #pragma unroll
    for (int j = 0; j < TJ; j++){
      const unsigned long long* kr = (const unsigned long long*)(sKC + j*132);
      unsigned long long kA0 = kr[tx*2],      kA1 = kr[tx*2 + 1];
      unsigned long long kB0 = kr[32 + tx*2], kB1 = kr[32 + tx*2 + 1];
      #pragma unroll
      for (int r = 0; r < 6; r++){
        float w = sW[(ty*6 + r)*33 + j];
        unsigned long long w2 = pk2(w, w);
        fma2(acc[r][0], w2, kA0); fma2(acc[r][1], w2, kA1);
        fma2(acc[r][2], w2, kB0); fma2(acc[r][3], w2, kB1);
      }
    }
  }

  // softmax denominators
  sLp[tid] = lp;
  __syncthreads();
  if (tid < BM) sInv[tid] = 1.f / (sLp[2*tid] + sLp[2*tid + 1]);
  __syncthreads();

  // epilogue: Eh = ex_h @ E (E stays L1-resident: 64KB, broadcast reads)
  unsigned long long eh[6][4];
  #pragma unroll
  for (int r = 0; r < 6; r++)
    #pragma unroll
    for (int c = 0; c < 4; c++) eh[r][c] = 0ull;

  const unsigned long long* E64 = (const unsigned long long*)E;
  #pragma unroll 4
  for (int k = 0; k < F; k++){
    const unsigned long long* er = E64 + k*64;
    unsigned long long eA0 = er[tx*2],      eA1 = er[tx*2 + 1];
    unsigned long long eB0 = er[32 + tx*2], eB1 = er[32 + tx*2 + 1];
    #pragma unroll
    for (int r = 0; r < 6; r++){
      float x = sEx[(ty*6 + r)*132 + k];
      unsigned long long x2 = pk2(x, x);
      fma2(eh[r][0], x2, eA0); fma2(eh[r][1], x2, eA1);
      fma2(eh[r][2], x2, eB0); fma2(eh[r][3], x2, eB1);
    }
  }

  // out = elu((acc/l) * Eh)
  #pragma unroll
  for (int r = 0; r < 6; r++){
    int row = ty*6 + r;
    int rg = row_start + row;
    if (rg < nex){
      float inv = sInv[row];
      float2 a0 = upk2(acc[r][0]), a1 = upk2(acc[r][1]);
      float2 a2 = upk2(acc[r][2]), a3 = upk2(acc[r][3]);
      float2 e0 = upk2(eh[r][0]),  e1 = upk2(eh[r][1]);
      float2 e2 = upk2(eh[r][2]),  e3 = upk2(eh[r][3]);
      float4 oA = make_float4(eluf(a0.x*inv*e0.x), eluf(a0.y*inv*e0.y),
                              eluf(a1.x*inv*e1.x), eluf(a1.y*inv*e1.y));
      float4 oB = make_float4(eluf(a2.x*inv*e2.x), eluf(a2.y*inv*e2.y),
                              eluf(a3.x*inv*e3.x), eluf(a3.y*inv*e3.y));
      *(float4*)(out + (size_t)rg*F + tx*4)      = oA;
      *(float4*)(out + (size_t)rg*F + 64 + tx*4) = oB;
    }
  }
}

// ---------------------------------------------------------------------------
extern "C" void kernel_launch(void* const* d_in, const int* in_sizes, int n_in,
                              void* d_out, int out_size)
{
  const float* exh = (const float*)d_in[0];   // [20000,128]
  const float* kch = (const float*)d_in[1];   // [1024,128]
  const int*   adj = (const int*)  d_in[2];   // [20000,1024]
  const float* W1  = (const float*)d_in[3];   // [128,128]
  const float* E   = (const float*)d_in[4];   // [128,128]
  const float* a   = (const float*)d_in[5];   // [256,1]
  float* out = (float*)d_out;

  int nex = in_sizes[0] / F;
  int nkc = in_sizes[1] / F;                  // 1024

  prep_kc<<<nkc, NT>>>(kch, W1, a);
  prep_v<<<1, NT>>>(W1, a, nkc);

  const int smem_bytes = (BM*132 + TJ*132 + BM*33 + NKC + F + 3*BM + 128) * 4;
  cudaFuncSetAttribute(gat_main, cudaFuncAttributeMaxDynamicSharedMemorySize, smem_bytes);
  int grid = (nex + BM - 1) / BM;
  gat_main<<<grid, NT, smem_bytes>>>(exh, adj, E, out, nex);
}

// round 2
// speedup vs baseline: 1.0010x; 1.0010x over previous
#include <cuda_runtime.h>
#include <math.h>

// Problem constants (fixed by the dataset): N_kc=1024, F=128.
#define NKC 1024
#define F   128
#define BM  48      // exercise rows per CTA
#define TJ  32      // kc tile (j dimension) per iteration
#define NT  128     // threads per CTA  (8 ty-groups x 16 tx)

// Scratch (device globals: no allocation allowed)
__device__ float g_kcWh[NKC*F];
__device__ float g_q[NKC];
__device__ float g_v1[F];
__device__ float g_qmax;

// ---- packed f32x2 helpers (FFMA2 — only reachable via PTX) ----
__device__ __forceinline__ unsigned long long pk2(float a, float b){
  unsigned long long r; asm("mov.b64 %0, {%1,%2};" : "=l"(r) : "f"(a), "f"(b)); return r;
}
__device__ __forceinline__ void fma2(unsigned long long &d, unsigned long long a, unsigned long long b){
  asm("fma.rn.f32x2 %0, %1, %2, %0;" : "+l"(d) : "l"(a), "l"(b));
}
__device__ __forceinline__ float2 upk2(unsigned long long v){
  float2 r; asm("mov.b64 {%0,%1}, %2;" : "=f"(r.x), "=f"(r.y) : "l"(v)); return r;
}
__device__ __forceinline__ float eluf(float x){ return x > 0.f ? x : expm1f(x); }

// ---------------------------------------------------------------------------
// prep_kc: kc_Wh[j,:] = kc_h[j,:] @ W1 ; q[j] = kc_Wh[j,:] . a2
// grid = NKC blocks, 128 threads
// ---------------------------------------------------------------------------
__global__ void prep_kc(const float* __restrict__ kch, const float* __restrict__ W1,
                        const float* __restrict__ a){
  __shared__ float sh[F];
  __shared__ float red[4];
  int j = blockIdx.x, f = threadIdx.x;
  sh[f] = kch[j*F + f];
  __syncthreads();
  float acc = 0.f;
  #pragma unroll 16
  for (int k = 0; k < F; k++) acc = fmaf(sh[k], W1[k*F + f], acc);
  g_kcWh[j*F + f] = acc;
  float t = acc * a[F + f];                    // a2 = a[128:256]
  #pragma unroll
  for (int o = 16; o > 0; o >>= 1) t += __shfl_xor_sync(0xffffffffu, t, o);
  if ((f & 31) == 0) red[f >> 5] = t;
  __syncthreads();
  if (f == 0) g_q[j] = red[0] + red[1] + red[2] + red[3];
}

// ---------------------------------------------------------------------------
// prep_v: v1 = W1 @ a1 (so p_i = ex_h[i] . v1), plus Qmax = max_j q[j]
// grid = 1 block, 128 threads
// ---------------------------------------------------------------------------
__global__ void prep_v(const float* __restrict__ W1, const float* __restrict__ a, int nkc){
  __shared__ float red[4];
  int k = threadIdx.x;
  float v = 0.f;
  #pragma unroll 16
  for (int f = 0; f < F; f++) v = fmaf(W1[k*F + f], a[f], v);   // a1 = a[0:128]
  g_v1[k] = v;
  float mq = -3.0e38f;
  for (int i = k; i < nkc; i += NT) mq = fmaxf(mq, g_q[i]);
  #pragma unroll
  for (int o = 16; o > 0; o >>= 1) mq = fmaxf(mq, __shfl_xor_sync(0xffffffffu, mq, o));
  if ((k & 31) == 0) red[k >> 5] = mq;
  __syncthreads();
  if (k == 0) g_qmax = fmaxf(fmaxf(red[0], red[1]), fmaxf(red[2], red[3]));
}

// ---------------------------------------------------------------------------
// Main fused kernel: per CTA, BM=48 exercise rows.
//   - p_r = ex_h[r].v1 ; m_r = lrelu(p_r + Qmax)  (global-bound stabilizer)
//   - loop over kc tiles of TJ=32:
//       w[r][j] = adj ? exp(lrelu(p_r+q_j) - m_r) : 0   (single pass, l += w)
//       acc[r][:] += w[r][j] * kc_Wh[j][:]              (FFMA2 register tiles 6x8)
//   - epilogue: Eh[r][:] = ex_h[r] @ E ; out = elu(acc/l * Eh)
// Thread map: ty=tid/16 -> rows ty*6..+5 ; tx=tid%16 -> cols tx*4..+3 and 64+tx*4..+3
// ---------------------------------------------------------------------------
__global__ void __launch_bounds__(NT, 3) gat_main(
    const float* __restrict__ exh, const int* __restrict__ adj,
    const float* __restrict__ E,   float* __restrict__ out, int nex)
{
  extern __shared__ float sm[];
  float* sEx  = sm;                 // [48][132] (pad 4 floats, keeps 16B align)
  float* sKC  = sEx + BM*132;       // [32][132]
  float* sW   = sKC + TJ*132;       // [48][33]
  float* sQ   = sW  + BM*33;        // [1024]
  float* sV   = sQ  + NKC;          // [128]
  float* sP   = sV  + F;            // [48]
  float* sM   = sP  + BM;           // [48]
  float* sInv = sM  + BM;           // [48]
  float* sLp  = sInv + BM;          // [128]

  const int tid = threadIdx.x;
  const int ty = tid >> 4, tx = tid & 15;
  const int row_start = blockIdx.x * BM;

  // ---- prologue: exercise tile, q, v1 into smem ----
  {
    float4* d4 = (float4*)sEx;
    const float4* s4 = (const float4*)exh;
    #pragma unroll
    for (int it = 0; it < 12; ++it){             // 48 rows * 32 float4 = 1536
      int i = tid + NT*it;
      int r = i >> 5, c = i & 31;
      int rg = row_start + r; if (rg > nex-1) rg = nex-1;
      d4[r*33 + c] = s4[(size_t)rg*32 + c];
    }
    ((float4*)sQ)[tid]       = ((const float4*)g_q)[tid];
    ((float4*)sQ)[tid + 128] = ((const float4*)g_q)[tid + 128];
    if (tid < 32) ((float4*)sV)[tid] = ((const float4*)g_v1)[tid];
  }
  __syncthreads();
  if (tid < BM){
    float p = 0.f;
    #pragma unroll 16
    for (int k = 0; k < F; k++) p = fmaf(sEx[tid*132 + k], sV[k], p);
    sP[tid] = p;
    float x = p + g_qmax;
    sM[tid] = x > 0.f ? x : 0.2f * x;            // lrelu, slope 0.2
  }
  __syncthreads();

  // w producers: 2 threads per row (96 threads), 16 j each
  float pr = 0.f, mr = 0.f;
  const int* abase = adj;
  const int prow = tid >> 1, phalf = tid & 1;
  if (tid < 96){
    pr = sP[prow]; mr = sM[prow];
    int rg = row_start + prow; if (rg > nex-1) rg = nex-1;
    abase = adj + (size_t)rg*NKC + phalf*16;
  }

  unsigned long long acc[6][4];
  #pragma unroll
  for (int r = 0; r < 6; r++)
    #pragma unroll
    for (int c = 0; c < 4; c++) acc[r][c] = 0ull;
  float lp = 0.f;

  // prefetch tile 0 (adj from DRAM, kc_Wh tile from L2)
  int4   apf[4];
  float4 kpf[8];
  const float4* kc4 = (const float4*)g_kcWh;
  if (tid < 96){
    const int4* ap = (const int4*)abase;
    #pragma unroll
    for (int u = 0; u < 4; u++) apf[u] = ap[u];
  }
  #pragma unroll
  for (int u = 0; u < 8; u++){                   // 32 rows * 32 float4 = 1024
    int i = tid + NT*u; int jr = i >> 5, c = i & 31;
    kpf[u] = kc4[jr*32 + c];
  }

  for (int t = 0; t < NKC/TJ; t++){
    __syncthreads();                             // previous tile fully consumed
    // commit prefetched kc tile
    #pragma unroll
    for (int u = 0; u < 8; u++){
      int i = tid + NT*u; int jr = i >> 5, c = i & 31;
      ((float4*)sKC)[jr*33 + c] = kpf[u];
    }
    // compute attention weights for this tile
    if (tid < 96){
      const float* qb = sQ + t*TJ + phalf*16;
      float* wb = sW + prow*33 + phalf*16;
      #pragma unroll
      for (int u = 0; u < 4; u++){
        int4 a4 = apf[u];
        #pragma unroll
        for (int v = 0; v < 4; v++){
          int av = (v==0) ? a4.x : (v==1) ? a4.y : (v==2) ? a4.z : a4.w;
          float x = pr + qb[u*4 + v];
          float e = x > 0.f ? x : 0.2f * x;
          float w = (av > 0) ? __expf(e - mr) : 0.f;
          lp += w;
          wb[u*4 + v] = w;
        }
      }
    }
    __syncthreads();
    // prefetch next tile while GEMM runs
    if (t < NKC/TJ - 1){
      if (tid < 96){
        const int4* ap = (const int4*)(abase + (t+1)*TJ);
        #pragma unroll
        for (int u = 0; u < 4; u++) apf[u] = ap[u];
      }
      #pragma unroll
      for (int u = 0; u < 8; u++){
        int i = tid + NT*u; int jr = i >> 5, c = i & 31;
        kpf[u] = kc4[(t+1)*(TJ*32) + jr*32 + c];
      }
    }
    // GEMM: acc += w * kc_Wh  (packed f32x2)
    #pragma unroll
    for (int j = 0; j < TJ; j++){
      const unsigned long long* kr = (const unsigned long long*)(sKC + j*132);
      unsigned long long kA0 = kr[tx*2],      kA1 = kr[tx*2 + 1];
      unsigned long long kB0 = kr[32 + tx*2], kB1 = kr[32 + tx*2 + 1];
      #pragma unroll
      for (int r = 0; r < 6; r++){
        float w = sW[(ty*6 + r)*33 + j];
        unsigned long long w2 = pk2(w, w);
        fma2(acc[r][0], w2, kA0); fma2(acc[r][1], w2, kA1);
        fma2(acc[r][2], w2, kB0); fma2(acc[r][3], w2, kB1);
      }
    }
  }

  // softmax denominators
  sLp[tid] = lp;
  __syncthreads();
  if (tid < BM) sInv[tid] = 1.f / (sLp[2*tid] + sLp[2*tid + 1]);
  __syncthreads();

  // epilogue: Eh = ex_h @ E (E stays L1-resident: 64KB, broadcast reads)
  unsigned long long eh[6][4];
  #pragma unroll
  for (int r = 0; r < 6; r++)
    #pragma unroll
    for (int c = 0; c < 4; c++) eh[r][c] = 0ull;

  const unsigned long long* E64 = (const unsigned long long*)E;
  #pragma unroll 4
  for (int k = 0; k < F; k++){
    const unsigned long long* er = E64 + k*64;
    unsigned long long eA0 = er[tx*2],      eA1 = er[tx*2 + 1];
    unsigned long long eB0 = er[32 + tx*2], eB1 = er[32 + tx*2 + 1];
    #pragma unroll
    for (int r = 0; r < 6; r++){
      float x = sEx[(ty*6 + r)*132 + k];
      unsigned long long x2 = pk2(x, x);
      fma2(eh[r][0], x2, eA0); fma2(eh[r][1], x2, eA1);
      fma2(eh[r][2], x2, eB0); fma2(eh[r][3], x2, eB1);
    }
  }

  // out = elu((acc/l) * Eh)
  #pragma unroll
  for (int r = 0; r < 6; r++){
    int row = ty*6 + r;
    int rg = row_start + row;
    if (rg < nex){
      float inv = sInv[row];
      float2 a0 = upk2(acc[r][0]), a1 = upk2(acc[r][1]);
      float2 a2 = upk2(acc[r][2]), a3 = upk2(acc[r][3]);
      float2 e0 = upk2(eh[r][0]),  e1 = upk2(eh[r][1]);
      float2 e2 = upk2(eh[r][2]),  e3 = upk2(eh[r][3]);
      float4 oA = make_float4(eluf(a0.x*inv*e0.x), eluf(a0.y*inv*e0.y),
                              eluf(a1.x*inv*e1.x), eluf(a1.y*inv*e1.y));
      float4 oB = make_float4(eluf(a2.x*inv*e2.x), eluf(a2.y*inv*e2.y),
                              eluf(a3.x*inv*e3.x), eluf(a3.y*inv*e3.y));
      *(float4*)(out + (size_t)rg*F + tx*4)      = oA;
      *(float4*)(out + (size_t)rg*F + 64 + tx*4) = oB;
    }
  }
}

// ---------------------------------------------------------------------------
extern "C" void kernel_launch(void* const* d_in, const int* in_sizes, int n_in,
                              void* d_out, int out_size)
{
  const float* exh = (const float*)d_in[0];   // [20000,128]
  const float* kch = (const float*)d_in[1];   // [1024,128]
  const int*   adj = (const int*)  d_in[2];   // [20000,1024]
  const float* W1  = (const float*)d_in[3];   // [128,128]
  const float* E   = (const float*)d_in[4];   // [128,128]
  const float* a   = (const float*)d_in[5];   // [256,1]
  float* out = (float*)d_out;

  int nex = in_sizes[0] / F;
  int nkc = in_sizes[1] / F;                  // 1024

  prep_kc<<<nkc, NT>>>(kch, W1, a);
  prep_v<<<1, NT>>>(W1, a, nkc);

  const int smem_bytes = (BM*132 + TJ*132 + BM*33 + NKC + F + 3*BM + 128) * 4;
  cudaFuncSetAttribute(gat_main, cudaFuncAttributeMaxDynamicSharedMemorySize, smem_bytes);
  int grid = (nex + BM - 1) / BM;
  gat_main<<<grid, NT, smem_bytes>>>(exh, adj, E, out, nex);
}